// round 15
// baseline (speedup 1.0000x reference)
#include <cuda_runtime.h>
#include <cuda_bf16.h>
#include <cuda_fp16.h>
#include <cstdint>
#include <mma.h>
using namespace nvcuda;

// Problem constants (fixed by the reference)
#define NN 20000
#define EE 320000
#define ET (NN + EE)          // edges incl. self loops = 340000
#define HEADS 8
#define MP 20096              // NN padded to multiple of 128 for tensor GEMM
#define NBLK ((NN + 255) / 256)   // 79 blocks for CSR scan

// ---------------- scratch (device globals: no allocation allowed) ----------
__device__ float g_feat[(size_t)MP * 1152];   // transformed features (+res cols)
__device__ __half g_feath[(size_t)MP * 1024]; // fp16 shadow for gathers
__device__ float g_act0[(size_t)NN * 256];    // activation after layer 0
__device__ float g_als[NN * HEADS];
__device__ float g_ald[NN * HEADS];
__device__ int g_src[ET];
__device__ int g_dst[ET];
__device__ int g_is64;
// CSR (dst-sorted adjacency)
__device__ int g_deg[NN];
__device__ int g_off[NN + 1];
__device__ int g_cur[NN];
__device__ int g_csr_src[ET];
__device__ int g_bsum[NBLK];
__device__ int g_boff[NBLK];

// bf16 split buffers. A: activations (MP x 256 max). B: ALL weights, segmented:
//   [W0|rW0] concat [64,512] @ 0 (32768 elems)
//   W1 [256,256] @ 32768 (65536)
//   [W2|rW2] concat [256,1152] @ 98304 (294912)  -> total 393216
__device__ __nv_bfloat16 g_Ah[(size_t)MP * 256];
__device__ __nv_bfloat16 g_Al[(size_t)MP * 256];
__device__ __nv_bfloat16 g_Bh[393216];
__device__ __nv_bfloat16 g_Bl[393216];

// ---------------- dtype detection: int64 vs int32 edge_index ---------------
__global__ void detect_kernel(const int* __restrict__ raw) {
    __shared__ int any;
    if (threadIdx.x == 0) any = 0;
    __syncthreads();
    for (int i = threadIdx.x; i < 2048; i += blockDim.x)
        if (raw[2 * i + 1] != 0) any = 1;
    __syncthreads();
    if (threadIdx.x == 0) g_is64 = (any == 0);
}

// ---------------- pad: zero A padding rows + degree array ------------------
__global__ void pad_kernel() {
    int i = blockIdx.x * blockDim.x + threadIdx.x;
    if (i < NN) g_deg[i] = 0;
    int tot = (MP - NN) * 256;
    if (i < tot) {
        g_Ah[(size_t)NN * 256 + i] = __float2bfloat16(0.f);
        g_Al[(size_t)NN * 256 + i] = __float2bfloat16(0.f);
    }
}

// ---------------- edge list build (+self loops) + degree histogram ---------
__global__ void build_edges_kernel(const void* __restrict__ eiraw) {
    int i = blockIdx.x * blockDim.x + threadIdx.x;
    if (i >= ET) return;
    int s, d;
    if (i < EE) {
        if (g_is64) {
            const long long* e = (const long long*)eiraw;
            s = (int)e[i];
            d = (int)e[EE + i];
        } else {
            const int* e = (const int*)eiraw;
            s = e[i];
            d = e[EE + i];
        }
        s = min(max(s, 0), NN - 1);
        d = min(max(d, 0), NN - 1);
    } else {
        s = d = i - EE;   // self loop
    }
    g_src[i] = s;
    g_dst[i] = d;
    atomicAdd(&g_deg[d], 1);
}

// ---------------- CSR: 3-phase parallel scan + scatter ---------------------
__global__ void csr_partial_kernel() {
    __shared__ int sh[256];
    int idx = blockIdx.x * 256 + threadIdx.x;
    int v = (idx < NN) ? g_deg[idx] : 0;
    sh[threadIdx.x] = v;
    __syncthreads();
    for (int off = 128; off; off >>= 1) {
        if (threadIdx.x < off) sh[threadIdx.x] += sh[threadIdx.x + off];
        __syncthreads();
    }
    if (threadIdx.x == 0) g_bsum[blockIdx.x] = sh[0];
}

__global__ void csr_scanb_kernel() {
    if (threadIdx.x == 0) {
        int run = 0;
        for (int i = 0; i < NBLK; i++) { g_boff[i] = run; run += g_bsum[i]; }
        g_off[NN] = ET;
    }
}

__global__ void csr_offsets_kernel() {
    __shared__ int sh[256];
    int idx = blockIdx.x * 256 + threadIdx.x;
    int v = (idx < NN) ? g_deg[idx] : 0;
    sh[threadIdx.x] = v;
    __syncthreads();
    for (int off = 1; off < 256; off <<= 1) {
        int u = (threadIdx.x >= off) ? sh[threadIdx.x - off] : 0;
        __syncthreads();
        sh[threadIdx.x] += u;
        __syncthreads();
    }
    if (idx < NN) {
        int excl = g_boff[blockIdx.x] + sh[threadIdx.x] - v;
        g_off[idx] = excl;
        g_cur[idx] = excl;
    }
}

__global__ void scatter_kernel() {
    int i = blockIdx.x * blockDim.x + threadIdx.x;
    if (i >= ET) return;
    int d = g_dst[i];
    int pos = atomicAdd(&g_cur[d], 1);
    g_csr_src[pos] = g_src[i];
}

// ---------------- fp32 -> bf16 hi/lo split (x-features, vectorized) --------
__global__ void split_kernel(const float* __restrict__ X,
                             __nv_bfloat16* __restrict__ H,
                             __nv_bfloat16* __restrict__ L,
                             int realElems, int totElems) {
    int i = (blockIdx.x * blockDim.x + threadIdx.x) * 4;
    if (i >= totElems) return;
    float4 v = (i < realElems) ? *(const float4*)&X[i] : make_float4(0.f, 0.f, 0.f, 0.f);
    __nv_bfloat162 h01 = {__float2bfloat16(v.x), __float2bfloat16(v.y)};
    __nv_bfloat162 h23 = {__float2bfloat16(v.z), __float2bfloat16(v.w)};
    __nv_bfloat162 l01 = {__float2bfloat16(v.x - __bfloat162float(h01.x)),
                          __float2bfloat16(v.y - __bfloat162float(h01.y))};
    __nv_bfloat162 l23 = {__float2bfloat16(v.z - __bfloat162float(h23.x)),
                          __float2bfloat16(v.w - __bfloat162float(h23.y))};
    *(__nv_bfloat162*)&H[i] = h01;
    *(__nv_bfloat162*)&H[i + 2] = h23;
    *(__nv_bfloat162*)&L[i] = l01;
    *(__nv_bfloat162*)&L[i + 2] = l23;
}

// ---------------- ALL weight matrices split + concat layouts ---------------
__global__ void wsplit_kernel(const float* __restrict__ W0, const float* __restrict__ rW0,
                              const float* __restrict__ W1, const float* __restrict__ W2,
                              const float* __restrict__ rW2) {
    int i4 = blockIdx.x * blockDim.x + threadIdx.x;    // float4 index, total 98304
    if (i4 >= 98304) return;
    const float4* src4; size_t dstElem;
    if (i4 < 8192) {                       // layer0 concat: 128 f4 per row
        int k = i4 >> 7, j = i4 & 127;
        if (j < 64) { src4 = (const float4*)W0 + (k * 64 + j);  dstElem = (size_t)k * 512 + j * 4; }
        else        { src4 = (const float4*)rW0 + (k * 64 + j - 64); dstElem = (size_t)k * 512 + 256 + (j - 64) * 4; }
    } else if (i4 < 24576) {               // W1 linear
        int e4 = i4 - 8192;
        src4 = (const float4*)W1 + e4;
        dstElem = 32768 + (size_t)e4 * 4;
    } else {                               // layer2 concat: 288 f4 per row
        int e4 = i4 - 24576;
        int k = e4 / 288, j = e4 - k * 288;
        if (j < 256) { src4 = (const float4*)W2 + (k * 256 + j); dstElem = 98304 + (size_t)k * 1152 + j * 4; }
        else         { src4 = (const float4*)rW2 + (k * 32 + j - 256); dstElem = 98304 + (size_t)k * 1152 + 1024 + (j - 256) * 4; }
    }
    float4 v = *src4;
    __nv_bfloat162 h01 = {__float2bfloat16(v.x), __float2bfloat16(v.y)};
    __nv_bfloat162 h23 = {__float2bfloat16(v.z), __float2bfloat16(v.w)};
    __nv_bfloat162 l01 = {__float2bfloat16(v.x - __bfloat162float(h01.x)),
                          __float2bfloat16(v.y - __bfloat162float(h01.y))};
    __nv_bfloat162 l23 = {__float2bfloat16(v.z - __bfloat162float(h23.x)),
                          __float2bfloat16(v.w - __bfloat162float(h23.y))};
    *(__nv_bfloat162*)&g_Bh[dstElem] = h01;
    *(__nv_bfloat162*)&g_Bh[dstElem + 2] = h23;
    *(__nv_bfloat162*)&g_Bl[dstElem] = l01;
    *(__nv_bfloat162*)&g_Bl[dstElem + 2] = l23;
}

// ---------------- tensor-core GEMM + fused epilogue ------------------------
// C[MP,N] = A @ B, split-bf16 3-product, register-prefetch double buffering.
// Epilogue (feature blocks only, col0 < S):
//   - fp16 shadow of C (stride S)
//   - attention logits per (node, head): Chead=32 -> 4 heads/block,
//     Chead=128 -> 1 head/block (no cross-block reduction needed).
struct __align__(256) SmemA { __nv_bfloat16 d[128][40]; };
struct __align__(256) SmemB { __nv_bfloat16 d[32][136]; };

__global__ void __launch_bounds__(256) gemm_tc_kernel(
    const __nv_bfloat16* __restrict__ Ah, const __nv_bfloat16* __restrict__ Al,
    const __nv_bfloat16* __restrict__ Bh, const __nv_bfloat16* __restrict__ Bl,
    float* __restrict__ C, __half* __restrict__ Cf16, int N, int K, int S,
    const float* __restrict__ a_s, const float* __restrict__ a_d, int Chead)
{
    __shared__ SmemA sAh, sAl;
    __shared__ SmemB sBh, sBl;
    int tid = threadIdx.x;
    int warp = tid >> 5;
    int wm = warp & 1, wn = warp >> 1;           // 2 x 4 warp grid
    int row0 = blockIdx.y * 128, col0 = blockIdx.x * 128;

    wmma::fragment<wmma::accumulator, 16, 16, 16, float> acc[4][2];
#pragma unroll
    for (int i = 0; i < 4; i++)
#pragma unroll
        for (int j = 0; j < 2; j++) wmma::fill_fragment(acc[i][j], 0.f);

    const int nk = K >> 5;
    uint4 rA[4], rB[4];

    auto loadRegs = [&](int k0) {
#pragma unroll
        for (int u = 0; u < 2; u++) {
            int v = tid + u * 256;
            int r = v >> 2, kk = (v & 3) * 8;
            size_t g = (size_t)(row0 + r) * K + k0 + kk;
            rA[u * 2]     = *(const uint4*)&Ah[g];
            rA[u * 2 + 1] = *(const uint4*)&Al[g];
        }
#pragma unroll
        for (int u = 0; u < 2; u++) {
            int v = tid + u * 256;
            int r = v >> 4, cc = (v & 15) * 8;
            size_t g = (size_t)(k0 + r) * N + col0 + cc;
            rB[u * 2]     = *(const uint4*)&Bh[g];
            rB[u * 2 + 1] = *(const uint4*)&Bl[g];
        }
    };
    auto storeRegs = [&]() {
#pragma unroll
        for (int u = 0; u < 2; u++) {
            int v = tid + u * 256;
            int r = v >> 2, kk = (v & 3) * 8;
            *(uint4*)&sAh.d[r][kk] = rA[u * 2];
            *(uint4*)&sAl.d[r][kk] = rA[u * 2 + 1];
        }
#pragma unroll
        for (int u = 0; u < 2; u++) {
            int v = tid + u * 256;
            int r = v >> 4, cc = (v & 15) * 8;
            *(uint4*)&sBh.d[r][cc] = rB[u * 2];
            *(uint4*)&sBl.d[r][cc] = rB[u * 2 + 1];
        }
    };

    loadRegs(0);
    for (int it = 0; it < nk; it++) {
        storeRegs();
        __syncthreads();
        if (it + 1 < nk) loadRegs((it + 1) * 32);   // overlap with compute below
#pragma unroll
        for (int ks = 0; ks < 32; ks += 16) {
            wmma::fragment<wmma::matrix_a, 16, 16, 16, __nv_bfloat16, wmma::row_major> fah[4], fal[4];
            wmma::fragment<wmma::matrix_b, 16, 16, 16, __nv_bfloat16, wmma::row_major> fbh[2], fbl[2];
#pragma unroll
            for (int i = 0; i < 4; i++) {
                wmma::load_matrix_sync(fah[i], &sAh.d[wm * 64 + i * 16][ks], 40);
                wmma::load_matrix_sync(fal[i], &sAl.d[wm * 64 + i * 16][ks], 40);
            }
#pragma unroll
            for (int j = 0; j < 2; j++) {
                wmma::load_matrix_sync(fbh[j], &sBh.d[ks][wn * 32 + j * 16], 136);
                wmma::load_matrix_sync(fbl[j], &sBl.d[ks][wn * 32 + j * 16], 136);
            }
#pragma unroll
            for (int i = 0; i < 4; i++)
#pragma unroll
                for (int j = 0; j < 2; j++) {
                    wmma::mma_sync(acc[i][j], fah[i], fbh[j], acc[i][j]);
                    wmma::mma_sync(acc[i][j], fal[i], fbh[j], acc[i][j]);
                    wmma::mma_sync(acc[i][j], fah[i], fbl[j], acc[i][j]);
                }
        }
        __syncthreads();
    }
#pragma unroll
    for (int i = 0; i < 4; i++)
#pragma unroll
        for (int j = 0; j < 2; j++)
            wmma::store_matrix_sync(&C[(size_t)(row0 + wm * 64 + i * 16) * N +
                                       col0 + wn * 32 + j * 16],
                                    acc[i][j], N, wmma::mem_row_major);

    if (col0 < S) {
        __syncthreads();   // other warps' C stores visible (same SM/L1)
        // fp16 shadow
        for (int idx = tid; idx < 4096; idx += 256) {
            int r = idx >> 5, cch = idx & 31;
            size_t gs = (size_t)(row0 + r) * N + col0 + cch * 4;
            float4 v = *(const float4*)&C[gs];
            __half2 a = __floats2half2_rn(v.x, v.y);
            __half2 b = __floats2half2_rn(v.z, v.w);
            size_t gd = (size_t)(row0 + r) * S + col0 + cch * 4;
            *(__half2*)&Cf16[gd] = a;
            *(__half2*)&Cf16[gd + 2] = b;
        }
        // fused attention logits (from L1-hot C tile)
        if (Chead == 32) {
            int r = tid >> 1, part = tid & 1;
            int node = row0 + r;
            if (node < NN) {
#pragma unroll
                for (int hl = 0; hl < 2; hl++) {
                    int hloc = part * 2 + hl;           // 0..3
                    int hglob = (col0 >> 5) + hloc;
                    const float* crow = &C[(size_t)node * N + col0 + hloc * 32];
                    const float* ws = a_s + hglob * 32;
                    const float* wd = a_d + hglob * 32;
                    float s1 = 0.f, s2 = 0.f;
#pragma unroll
                    for (int c = 0; c < 32; c++) { float v = crow[c]; s1 += v * ws[c]; s2 += v * wd[c]; }
                    g_als[node * 8 + hglob] = s1;
                    g_ald[node * 8 + hglob] = s2;
                }
            }
        } else {   // Chead == 128: one head per block
            if (tid < 128) {
                int node = row0 + tid;
                if (node < NN) {
                    int hglob = col0 >> 7;
                    const float* crow = &C[(size_t)node * N + col0];
                    const float* ws = a_s + hglob * 128;
                    const float* wd = a_d + hglob * 128;
                    float s1 = 0.f, s2 = 0.f;
                    for (int c = 0; c < 128; c++) { float v = crow[c]; s1 += v * ws[c]; s2 += v * wd[c]; }
                    g_als[node * 8 + hglob] = s1;
                    g_ald[node * 8 + hglob] = s2;
                }
            }
        }
    }
}

// ---------------- fused aggregation + LN + residual + ELU (layers 0/1) -----
// Warp per dst node holds the full 256-dim row: softmax over neighbors, then
// LayerNorm via warp butterfly, +sig*res, ELU, write act + bf16 splits.
__global__ void __launch_bounds__(256) aggfin_small_kernel(
    const __half* __restrict__ feath, const float* __restrict__ bias,
    const float* __restrict__ lng, const float* __restrict__ lnb,
    const float* __restrict__ res, int resStride, const float* __restrict__ rb,
    const float* __restrict__ rw, float* __restrict__ outAct,
    __nv_bfloat16* __restrict__ outH, __nv_bfloat16* __restrict__ outL)
{
    int wid = (blockIdx.x * blockDim.x + threadIdx.x) >> 5;
    if (wid >= NN) return;
    int lane = threadIdx.x & 31;
    int h = lane & 7;
    int beg = g_off[wid], end = g_off[wid + 1];
    float ald_h = g_ald[wid * HEADS + h];

    float m = -1e30f;
    for (int i = beg + (lane >> 3); i < end; i += 4) {
        int s = g_csr_src[i];
        float ev = g_als[s * HEADS + h] + ald_h;
        ev = ev > 0.f ? ev : 0.2f * ev;
        m = fmaxf(m, ev);
    }
    m = fmaxf(m, __shfl_xor_sync(0xffffffffu, m, 8));
    m = fmaxf(m, __shfl_xor_sync(0xffffffffu, m, 16));
    float ssum = 0.f;
    for (int i = beg + (lane >> 3); i < end; i += 4) {
        int s = g_csr_src[i];
        float ev = g_als[s * HEADS + h] + ald_h;
        ev = ev > 0.f ? ev : 0.2f * ev;
        ssum += expf(ev - m);
    }
    ssum += __shfl_xor_sync(0xffffffffu, ssum, 8);
    ssum += __shfl_xor_sync(0xffffffffu, ssum, 16);
    float inv = 1.f / (ssum + 1e-16f);

    float acc[8] = {0.f, 0.f, 0.f, 0.f, 0.f, 0.f, 0.f, 0.f};
    for (int i = beg; i < end; i++) {
        int s = g_csr_src[i];
        float ev = g_als[s * HEADS + h] + ald_h;
        ev = ev > 0.f ? ev : 0.2f * ev;
        float alpha = expf(ev - m) * inv;
        const __half* f = feath + (size_t)s * 256;
#pragma unroll
        for (int hh = 0; hh < 8; hh++) {
            float a = __shfl_sync(0xffffffffu, alpha, hh);
            acc[hh] += a * __half2float(f[hh * 32 + lane]);
        }
    }

    // +bias, LayerNorm over the warp-held 256-dim row
    float gval[8];
    float s1 = 0.f, s2 = 0.f;
#pragma unroll
    for (int hh = 0; hh < 8; hh++) {
        float g = acc[hh] + bias[hh * 32 + lane];
        gval[hh] = g; s1 += g; s2 += g * g;
    }
#pragma unroll
    for (int o = 16; o; o >>= 1) {
        s1 += __shfl_xor_sync(0xffffffffu, s1, o);
        s2 += __shfl_xor_sync(0xffffffffu, s2, o);
    }
    float mu = s1 * (1.f / 256.f);
    float var = s2 * (1.f / 256.f) - mu * mu;
    float rs = rsqrtf(var + 1e-5f);
    float sig = 1.f / (1.f + expf(-rw[0]));

#pragma unroll
    for (int hh = 0; hh < 8; hh++) {
        int c = hh * 32 + lane;
        float y = (gval[hh] - mu) * rs * lng[c] + lnb[c];
        float r = res[(size_t)wid * resStride + c];
        if (rb) r += rb[c];
        float z = y + sig * r;
        z = z > 0.f ? z : expm1f(z);   // elu
        size_t o = (size_t)wid * 256 + c;
        if (outAct) outAct[o] = z;
        __nv_bfloat16 zh = __float2bfloat16(z);
        outH[o] = zh;
        outL[o] = __float2bfloat16(z - __bfloat162float(zh));
    }
}

// ---------------- fused aggregation + LN + residual (layer 2, final) -------
__global__ void __launch_bounds__(256) aggfin_big_kernel(
    const __half* __restrict__ feath, const float* __restrict__ bias,
    const float* __restrict__ lng, const float* __restrict__ lnb,
    const float* __restrict__ res, int resStride, const float* __restrict__ rb,
    const float* __restrict__ rw, float* __restrict__ out)
{
    int wid = (blockIdx.x * blockDim.x + threadIdx.x) >> 5;
    if (wid >= NN) return;
    int lane = threadIdx.x & 31;
    int h = lane & 7;
    int beg = g_off[wid], end = g_off[wid + 1];
    float ald_h = g_ald[wid * HEADS + h];

    float m = -1e30f;
    for (int i = beg + (lane >> 3); i < end; i += 4) {
        int s = g_csr_src[i];
        float ev = g_als[s * HEADS + h] + ald_h;
        ev = ev > 0.f ? ev : 0.2f * ev;
        m = fmaxf(m, ev);
    }
    m = fmaxf(m, __shfl_xor_sync(0xffffffffu, m, 8));
    m = fmaxf(m, __shfl_xor_sync(0xffffffffu, m, 16));
    float ssum = 0.f;
    for (int i = beg + (lane >> 3); i < end; i += 4) {
        int s = g_csr_src[i];
        float ev = g_als[s * HEADS + h] + ald_h;
        ev = ev > 0.f ? ev : 0.2f * ev;
        ssum += expf(ev - m);
    }
    ssum += __shfl_xor_sync(0xffffffffu, ssum, 8);
    ssum += __shfl_xor_sync(0xffffffffu, ssum, 16);
    float inv = 0.125f / (ssum + 1e-16f);   // fold mean-over-heads

    float acc[4] = {0.f, 0.f, 0.f, 0.f};
    for (int i = beg; i < end; i++) {
        int s = g_csr_src[i];
        float ev = g_als[s * HEADS + h] + ald_h;
        ev = ev > 0.f ? ev : 0.2f * ev;
        float alpha = expf(ev - m) * inv;
        const __half* f = feath + (size_t)s * 1024;
#pragma unroll
        for (int hh = 0; hh < 8; hh++) {
            float a = __shfl_sync(0xffffffffu, alpha, hh);
            const __half* fh = f + hh * 128;
#pragma unroll
            for (int ch = 0; ch < 4; ch++)
                acc[ch] += a * __half2float(fh[ch * 32 + lane]);
        }
    }

    // +bias, LN over warp-held 128-dim row, +sig*res (no elu)
    float gval[4];
    float s1 = 0.f, s2 = 0.f;
#pragma unroll
    for (int ch = 0; ch < 4; ch++) {
        float g = acc[ch] + bias[ch * 32 + lane];
        gval[ch] = g; s1 += g; s2 += g * g;
    }
#pragma unroll
    for (int o = 16; o; o >>= 1) {
        s1 += __shfl_xor_sync(0xffffffffu, s1, o);
        s2 += __shfl_xor_sync(0xffffffffu, s2, o);
    }
    float mu = s1 * (1.f / 128.f);
    float var = s2 * (1.f / 128.f) - mu * mu;
    float rs = rsqrtf(var + 1e-5f);
    float sig = 1.f / (1.f + expf(-rw[0]));

#pragma unroll
    for (int ch = 0; ch < 4; ch++) {
        int c = ch * 32 + lane;
        float y = (gval[ch] - mu) * rs * lng[c] + lnb[c];
        float r = res[(size_t)wid * resStride + c] + rb[c];
        out[(size_t)wid * 128 + c] = y + sig * r;
    }
}

// ---------------------------------------------------------------------------
extern "C" void kernel_launch(void* const* d_in, const int* in_sizes, int n_in,
                              void* d_out, int out_size) {
    const float* x   = (const float*)d_in[0];
    const void*  ei  = d_in[1];                   // int32 or int64, detected on device
    const float* W0  = (const float*)d_in[2];
    const float* b0  = (const float*)d_in[3];
    const float* as0 = (const float*)d_in[4];
    const float* ad0 = (const float*)d_in[5];
    const float* lng0= (const float*)d_in[6];
    const float* lnb0= (const float*)d_in[7];
    const float* rW0 = (const float*)d_in[8];
    const float* rb0 = (const float*)d_in[9];
    const float* rw0 = (const float*)d_in[10];
    const float* W1  = (const float*)d_in[11];
    const float* b1  = (const float*)d_in[12];
    const float* as1 = (const float*)d_in[13];
    const float* ad1 = (const float*)d_in[14];
    const float* lng1= (const float*)d_in[15];
    const float* lnb1= (const float*)d_in[16];
    const float* rw1 = (const float*)d_in[17];
    const float* W2  = (const float*)d_in[18];
    const float* b2  = (const float*)d_in[19];
    const float* as2 = (const float*)d_in[20];
    const float* ad2 = (const float*)d_in[21];
    const float* lng2= (const float*)d_in[22];
    const float* lnb2= (const float*)d_in[23];
    const float* rW2 = (const float*)d_in[24];
    const float* rb2 = (const float*)d_in[25];
    const float* rw2 = (const float*)d_in[26];

    float *feat, *act0;
    __half *feath;
    __nv_bfloat16 *Ah, *Al, *Bh, *Bl;
    cudaGetSymbolAddress((void**)&feat, g_feat);
    cudaGetSymbolAddress((void**)&feath, g_feath);
    cudaGetSymbolAddress((void**)&act0, g_act0);
    cudaGetSymbolAddress((void**)&Ah, g_Ah);
    cudaGetSymbolAddress((void**)&Al, g_Al);
    cudaGetSymbolAddress((void**)&Bh, g_Bh);
    cudaGetSymbolAddress((void**)&Bl, g_Bl);

    const int TB = 256;
    detect_kernel<<<1, 256>>>((const int*)ei);
    pad_kernel<<<((MP - NN) * 256 + TB - 1) / TB, TB>>>();
    build_edges_kernel<<<(ET + TB - 1) / TB, TB>>>(ei);
    wsplit_kernel<<<(98304 + TB - 1) / TB, TB>>>(W0, rW0, W1, W2, rW2);
    split_kernel<<<(MP * 64 / 4 + TB - 1) / TB, TB>>>(x, Ah, Al, NN * 64, MP * 64);

    int aggBlocks = (NN * 32 + TB - 1) / TB;
    const int MROWS = MP / 128;   // 157

    // ---------------- layer 0 ----------------
    gemm_tc_kernel<<<dim3(4, MROWS), 256>>>(Ah, Al, Bh, Bl, feat, feath, 512, 64, 256, as0, ad0, 32);
    // CSR build (needed before agg)
    csr_partial_kernel<<<NBLK, 256>>>();
    csr_scanb_kernel<<<1, 32>>>();
    csr_offsets_kernel<<<NBLK, 256>>>();
    scatter_kernel<<<(ET + TB - 1) / TB, TB>>>();
    aggfin_small_kernel<<<aggBlocks, TB>>>(feath, b0, lng0, lnb0, feat + 256, 512, rb0, rw0, act0, Ah, Al);

    // ---------------- layer 1 ----------------
    gemm_tc_kernel<<<dim3(2, MROWS), 256>>>(Ah, Al, Bh + 32768, Bl + 32768, feat, feath, 256, 256, 256, as1, ad1, 32);
    aggfin_small_kernel<<<aggBlocks, TB>>>(feath, b1, lng1, lnb1, act0, 256, nullptr, rw1, nullptr, Ah, Al);

    // ---------------- layer 2 ----------------
    gemm_tc_kernel<<<dim3(9, MROWS), 256>>>(Ah, Al, Bh + 98304, Bl + 98304, feat, feath, 1152, 256, 1024, as2, ad2, 128);
    aggfin_big_kernel<<<aggBlocks, TB>>>(feath, b2, lng2, lnb2, feat + 1024, 1152, rb2, rw2, (float*)d_out);
}

// round 16
// speedup vs baseline: 1.1166x; 1.1166x over previous
#include <cuda_runtime.h>
#include <cuda_bf16.h>
#include <cuda_fp16.h>
#include <cstdint>
#include <mma.h>
using namespace nvcuda;

// Problem constants (fixed by the reference)
#define NN 20000
#define EE 320000
#define ET (NN + EE)          // edges incl. self loops = 340000
#define HEADS 8
#define MP 20096              // NN padded to multiple of 128 for tensor GEMM
#define NBLK ((NN + 255) / 256)   // 79 blocks for CSR scan

// ---------------- scratch (device globals: no allocation allowed) ----------
__device__ float g_feat[(size_t)MP * 1152];   // transformed features (+res cols)
__device__ __half g_feath[(size_t)MP * 1024]; // fp16 shadow for gathers
__device__ float g_act0[(size_t)NN * 256];    // activation after layer 0
__device__ float g_als[NN * HEADS];
__device__ float g_ald[NN * HEADS];
__device__ int g_src[ET];
__device__ int g_dst[ET];
__device__ int g_is64;
// CSR (dst-sorted adjacency)
__device__ int g_deg[NN];
__device__ int g_off[NN + 1];
__device__ int g_cur[NN];
__device__ int g_csr_src[ET];
__device__ int g_bsum[NBLK];
__device__ int g_boff[NBLK];

// fp16 split buffers. A: activations hi+lo (exact). B: weights rounded to fp16:
//   [W0|rW0] concat [64,512] @ 0 (32768 elems)
//   W1 [256,256] @ 32768 (65536)
//   [W2|rW2] concat [256,1152] @ 98304 (294912)  -> total 393216
__device__ __half g_Ah[(size_t)MP * 256];
__device__ __half g_Al[(size_t)MP * 256];
__device__ __half g_Bh[393216];

// ---------------- dtype detection: int64 vs int32 edge_index ---------------
__global__ void detect_kernel(const int* __restrict__ raw) {
    __shared__ int any;
    if (threadIdx.x == 0) any = 0;
    __syncthreads();
    for (int i = threadIdx.x; i < 2048; i += blockDim.x)
        if (raw[2 * i + 1] != 0) any = 1;
    __syncthreads();
    if (threadIdx.x == 0) g_is64 = (any == 0);
}

// ---------------- pad: zero A padding rows + degree array ------------------
__global__ void pad_kernel() {
    int i = blockIdx.x * blockDim.x + threadIdx.x;
    if (i < NN) g_deg[i] = 0;
    int tot = (MP - NN) * 256;
    if (i < tot) {
        g_Ah[(size_t)NN * 256 + i] = __float2half(0.f);
        g_Al[(size_t)NN * 256 + i] = __float2half(0.f);
    }
}

// ---------------- edge list build (+self loops) + degree histogram ---------
__global__ void build_edges_kernel(const void* __restrict__ eiraw) {
    int i = blockIdx.x * blockDim.x + threadIdx.x;
    if (i >= ET) return;
    int s, d;
    if (i < EE) {
        if (g_is64) {
            const long long* e = (const long long*)eiraw;
            s = (int)e[i];
            d = (int)e[EE + i];
        } else {
            const int* e = (const int*)eiraw;
            s = e[i];
            d = e[EE + i];
        }
        s = min(max(s, 0), NN - 1);
        d = min(max(d, 0), NN - 1);
    } else {
        s = d = i - EE;   // self loop
    }
    g_src[i] = s;
    g_dst[i] = d;
    atomicAdd(&g_deg[d], 1);
}

// ---------------- CSR: 3-phase parallel scan + scatter ---------------------
__global__ void csr_partial_kernel() {
    __shared__ int sh[256];
    int idx = blockIdx.x * 256 + threadIdx.x;
    int v = (idx < NN) ? g_deg[idx] : 0;
    sh[threadIdx.x] = v;
    __syncthreads();
    for (int off = 128; off; off >>= 1) {
        if (threadIdx.x < off) sh[threadIdx.x] += sh[threadIdx.x + off];
        __syncthreads();
    }
    if (threadIdx.x == 0) g_bsum[blockIdx.x] = sh[0];
}

__global__ void csr_scanb_kernel() {
    if (threadIdx.x == 0) {
        int run = 0;
        for (int i = 0; i < NBLK; i++) { g_boff[i] = run; run += g_bsum[i]; }
        g_off[NN] = ET;
    }
}

__global__ void csr_offsets_kernel() {
    __shared__ int sh[256];
    int idx = blockIdx.x * 256 + threadIdx.x;
    int v = (idx < NN) ? g_deg[idx] : 0;
    sh[threadIdx.x] = v;
    __syncthreads();
    for (int off = 1; off < 256; off <<= 1) {
        int u = (threadIdx.x >= off) ? sh[threadIdx.x - off] : 0;
        __syncthreads();
        sh[threadIdx.x] += u;
        __syncthreads();
    }
    if (idx < NN) {
        int excl = g_boff[blockIdx.x] + sh[threadIdx.x] - v;
        g_off[idx] = excl;
        g_cur[idx] = excl;
    }
}

__global__ void scatter_kernel() {
    int i = blockIdx.x * blockDim.x + threadIdx.x;
    if (i >= ET) return;
    int d = g_dst[i];
    int pos = atomicAdd(&g_cur[d], 1);
    g_csr_src[pos] = g_src[i];
}

// ---------------- fp32 -> fp16 hi/lo split (x-features, vectorized) --------
__global__ void split_kernel(const float* __restrict__ X,
                             __half* __restrict__ H,
                             __half* __restrict__ L,
                             int realElems, int totElems) {
    int i = (blockIdx.x * blockDim.x + threadIdx.x) * 4;
    if (i >= totElems) return;
    float4 v = (i < realElems) ? *(const float4*)&X[i] : make_float4(0.f, 0.f, 0.f, 0.f);
    __half hx = __float2half_rn(v.x), hy = __float2half_rn(v.y);
    __half hz = __float2half_rn(v.z), hw = __float2half_rn(v.w);
    __half2 h01 = {hx, hy}, h23 = {hz, hw};
    __half2 l01 = {__float2half_rn(v.x - __half2float(hx)),
                   __float2half_rn(v.y - __half2float(hy))};
    __half2 l23 = {__float2half_rn(v.z - __half2float(hz)),
                   __float2half_rn(v.w - __half2float(hw))};
    *(__half2*)&H[i] = h01;
    *(__half2*)&H[i + 2] = h23;
    *(__half2*)&L[i] = l01;
    *(__half2*)&L[i + 2] = l23;
}

// ---------------- ALL weight matrices: fp16 round + concat layouts ---------
__global__ void wsplit_kernel(const float* __restrict__ W0, const float* __restrict__ rW0,
                              const float* __restrict__ W1, const float* __restrict__ W2,
                              const float* __restrict__ rW2) {
    int i4 = blockIdx.x * blockDim.x + threadIdx.x;    // float4 index, total 98304
    if (i4 >= 98304) return;
    const float4* src4; size_t dstElem;
    if (i4 < 8192) {                       // layer0 concat: 128 f4 per row
        int k = i4 >> 7, j = i4 & 127;
        if (j < 64) { src4 = (const float4*)W0 + (k * 64 + j);  dstElem = (size_t)k * 512 + j * 4; }
        else        { src4 = (const float4*)rW0 + (k * 64 + j - 64); dstElem = (size_t)k * 512 + 256 + (j - 64) * 4; }
    } else if (i4 < 24576) {               // W1 linear
        int e4 = i4 - 8192;
        src4 = (const float4*)W1 + e4;
        dstElem = 32768 + (size_t)e4 * 4;
    } else {                               // layer2 concat: 288 f4 per row
        int e4 = i4 - 24576;
        int k = e4 / 288, j = e4 - k * 288;
        if (j < 256) { src4 = (const float4*)W2 + (k * 256 + j); dstElem = 98304 + (size_t)k * 1152 + j * 4; }
        else         { src4 = (const float4*)rW2 + (k * 32 + j - 256); dstElem = 98304 + (size_t)k * 1152 + 1024 + (j - 256) * 4; }
    }
    float4 v = *src4;
    __half2 h01 = {__float2half_rn(v.x), __float2half_rn(v.y)};
    __half2 h23 = {__float2half_rn(v.z), __float2half_rn(v.w)};
    *(__half2*)&g_Bh[dstElem] = h01;
    *(__half2*)&g_Bh[dstElem + 2] = h23;
}

// ---------------- tensor-core GEMM + fused epilogue ------------------------
// C[MP,N] = A @ Bh, split-fp16 2-product (exact in A; error = B fp16 round).
// Block 128x128, BK=32, 8 warps, register-prefetch double buffering.
// Epilogue (feature blocks only, col0 < S): fp16 shadow + attention logits.
struct __align__(256) SmemA { __half d[128][40]; };
struct __align__(256) SmemB { __half d[32][136]; };

__global__ void __launch_bounds__(256) gemm_tc_kernel(
    const __half* __restrict__ Ah, const __half* __restrict__ Al,
    const __half* __restrict__ Bh,
    float* __restrict__ C, __half* __restrict__ Cf16, int N, int K, int S,
    const float* __restrict__ a_s, const float* __restrict__ a_d, int Chead)
{
    __shared__ SmemA sAh, sAl;
    __shared__ SmemB sBh;
    int tid = threadIdx.x;
    int warp = tid >> 5;
    int wm = warp & 1, wn = warp >> 1;           // 2 x 4 warp grid
    int row0 = blockIdx.y * 128, col0 = blockIdx.x * 128;

    wmma::fragment<wmma::accumulator, 16, 16, 16, float> acc[4][2];
#pragma unroll
    for (int i = 0; i < 4; i++)
#pragma unroll
        for (int j = 0; j < 2; j++) wmma::fill_fragment(acc[i][j], 0.f);

    const int nk = K >> 5;
    uint4 rA[4], rB[2];

    auto loadRegs = [&](int k0) {
#pragma unroll
        for (int u = 0; u < 2; u++) {
            int v = tid + u * 256;
            int r = v >> 2, kk = (v & 3) * 8;
            size_t g = (size_t)(row0 + r) * K + k0 + kk;
            rA[u * 2]     = *(const uint4*)&Ah[g];
            rA[u * 2 + 1] = *(const uint4*)&Al[g];
        }
#pragma unroll
        for (int u = 0; u < 2; u++) {
            int v = tid + u * 256;
            int r = v >> 4, cc = (v & 15) * 8;
            size_t g = (size_t)(k0 + r) * N + col0 + cc;
            rB[u] = *(const uint4*)&Bh[g];
        }
    };
    auto storeRegs = [&]() {
#pragma unroll
        for (int u = 0; u < 2; u++) {
            int v = tid + u * 256;
            int r = v >> 2, kk = (v & 3) * 8;
            *(uint4*)&sAh.d[r][kk] = rA[u * 2];
            *(uint4*)&sAl.d[r][kk] = rA[u * 2 + 1];
        }
#pragma unroll
        for (int u = 0; u < 2; u++) {
            int v = tid + u * 256;
            int r = v >> 4, cc = (v & 15) * 8;
            *(uint4*)&sBh.d[r][cc] = rB[u];
        }
    };

    loadRegs(0);
    for (int it = 0; it < nk; it++) {
        storeRegs();
        __syncthreads();
        if (it + 1 < nk) loadRegs((it + 1) * 32);   // overlap with compute below
#pragma unroll
        for (int ks = 0; ks < 32; ks += 16) {
            wmma::fragment<wmma::matrix_a, 16, 16, 16, __half, wmma::row_major> fah[4], fal[4];
            wmma::fragment<wmma::matrix_b, 16, 16, 16, __half, wmma::row_major> fbh[2];
#pragma unroll
            for (int i = 0; i < 4; i++) {
                wmma::load_matrix_sync(fah[i], &sAh.d[wm * 64 + i * 16][ks], 40);
                wmma::load_matrix_sync(fal[i], &sAl.d[wm * 64 + i * 16][ks], 40);
            }
#pragma unroll
            for (int j = 0; j < 2; j++)
                wmma::load_matrix_sync(fbh[j], &sBh.d[ks][wn * 32 + j * 16], 136);
#pragma unroll
            for (int i = 0; i < 4; i++)
#pragma unroll
                for (int j = 0; j < 2; j++) {
                    wmma::mma_sync(acc[i][j], fah[i], fbh[j], acc[i][j]);
                    wmma::mma_sync(acc[i][j], fal[i], fbh[j], acc[i][j]);
                }
        }
        __syncthreads();
    }
#pragma unroll
    for (int i = 0; i < 4; i++)
#pragma unroll
        for (int j = 0; j < 2; j++)
            wmma::store_matrix_sync(&C[(size_t)(row0 + wm * 64 + i * 16) * N +
                                       col0 + wn * 32 + j * 16],
                                    acc[i][j], N, wmma::mem_row_major);

    if (col0 < S) {
        __syncthreads();   // other warps' C stores visible (same SM/L1)
        // fp16 shadow
        for (int idx = tid; idx < 4096; idx += 256) {
            int r = idx >> 5, cch = idx & 31;
            size_t gs = (size_t)(row0 + r) * N + col0 + cch * 4;
            float4 v = *(const float4*)&C[gs];
            __half2 a = __floats2half2_rn(v.x, v.y);
            __half2 b = __floats2half2_rn(v.z, v.w);
            size_t gd = (size_t)(row0 + r) * S + col0 + cch * 4;
            *(__half2*)&Cf16[gd] = a;
            *(__half2*)&Cf16[gd + 2] = b;
        }
        // fused attention logits (from L1-hot C tile)
        if (Chead == 32) {
            int r = tid >> 1, part = tid & 1;
            int node = row0 + r;
            if (node < NN) {
#pragma unroll
                for (int hl = 0; hl < 2; hl++) {
                    int hloc = part * 2 + hl;           // 0..3
                    int hglob = (col0 >> 5) + hloc;
                    const float* crow = &C[(size_t)node * N + col0 + hloc * 32];
                    const float* ws = a_s + hglob * 32;
                    const float* wd = a_d + hglob * 32;
                    float s1 = 0.f, s2 = 0.f;
#pragma unroll
                    for (int c = 0; c < 32; c++) { float v = crow[c]; s1 += v * ws[c]; s2 += v * wd[c]; }
                    g_als[node * 8 + hglob] = s1;
                    g_ald[node * 8 + hglob] = s2;
                }
            }
        } else {   // Chead == 128: one head per block
            if (tid < 128) {
                int node = row0 + tid;
                if (node < NN) {
                    int hglob = col0 >> 7;
                    const float* crow = &C[(size_t)node * N + col0];
                    const float* ws = a_s + hglob * 128;
                    const float* wd = a_d + hglob * 128;
                    float s1 = 0.f, s2 = 0.f;
                    for (int c = 0; c < 128; c++) { float v = crow[c]; s1 += v * ws[c]; s2 += v * wd[c]; }
                    g_als[node * 8 + hglob] = s1;
                    g_ald[node * 8 + hglob] = s2;
                }
            }
        }
    }
}

// ---------------- fused aggregation + LN + residual + ELU (layers 0/1) -----
__global__ void __launch_bounds__(256) aggfin_small_kernel(
    const __half* __restrict__ feath, const float* __restrict__ bias,
    const float* __restrict__ lng, const float* __restrict__ lnb,
    const float* __restrict__ res, int resStride, const float* __restrict__ rb,
    const float* __restrict__ rw, float* __restrict__ outAct,
    __half* __restrict__ outH, __half* __restrict__ outL)
{
    int wid = (blockIdx.x * blockDim.x + threadIdx.x) >> 5;
    if (wid >= NN) return;
    int lane = threadIdx.x & 31;
    int h = lane & 7;
    int beg = g_off[wid], end = g_off[wid + 1];
    float ald_h = g_ald[wid * HEADS + h];

    float m = -1e30f;
    for (int i = beg + (lane >> 3); i < end; i += 4) {
        int s = g_csr_src[i];
        float ev = g_als[s * HEADS + h] + ald_h;
        ev = ev > 0.f ? ev : 0.2f * ev;
        m = fmaxf(m, ev);
    }
    m = fmaxf(m, __shfl_xor_sync(0xffffffffu, m, 8));
    m = fmaxf(m, __shfl_xor_sync(0xffffffffu, m, 16));
    float ssum = 0.f;
    for (int i = beg + (lane >> 3); i < end; i += 4) {
        int s = g_csr_src[i];
        float ev = g_als[s * HEADS + h] + ald_h;
        ev = ev > 0.f ? ev : 0.2f * ev;
        ssum += expf(ev - m);
    }
    ssum += __shfl_xor_sync(0xffffffffu, ssum, 8);
    ssum += __shfl_xor_sync(0xffffffffu, ssum, 16);
    float inv = 1.f / (ssum + 1e-16f);

    float acc[8] = {0.f, 0.f, 0.f, 0.f, 0.f, 0.f, 0.f, 0.f};
    for (int i = beg; i < end; i++) {
        int s = g_csr_src[i];
        float ev = g_als[s * HEADS + h] + ald_h;
        ev = ev > 0.f ? ev : 0.2f * ev;
        float alpha = expf(ev - m) * inv;
        const __half* f = feath + (size_t)s * 256;
#pragma unroll
        for (int hh = 0; hh < 8; hh++) {
            float a = __shfl_sync(0xffffffffu, alpha, hh);
            acc[hh] += a * __half2float(f[hh * 32 + lane]);
        }
    }

    // +bias, LayerNorm over the warp-held 256-dim row
    float gval[8];
    float s1 = 0.f, s2 = 0.f;
#pragma unroll
    for (int hh = 0; hh < 8; hh++) {
        float g = acc[hh] + bias[hh * 32 + lane];
        gval[hh] = g; s1 += g; s2 += g * g;
    }
#pragma unroll
    for (int o = 16; o; o >>= 1) {
        s1 += __shfl_xor_sync(0xffffffffu, s1, o);
        s2 += __shfl_xor_sync(0xffffffffu, s2, o);
    }
    float mu = s1 * (1.f / 256.f);
    float var = s2 * (1.f / 256.f) - mu * mu;
    float rs = rsqrtf(var + 1e-5f);
    float sig = 1.f / (1.f + expf(-rw[0]));

#pragma unroll
    for (int hh = 0; hh < 8; hh++) {
        int c = hh * 32 + lane;
        float y = (gval[hh] - mu) * rs * lng[c] + lnb[c];
        float r = res[(size_t)wid * resStride + c];
        if (rb) r += rb[c];
        float z = y + sig * r;
        z = z > 0.f ? z : expm1f(z);   // elu
        size_t o = (size_t)wid * 256 + c;
        if (outAct) outAct[o] = z;
        __half zh = __float2half_rn(z);
        outH[o] = zh;
        outL[o] = __float2half_rn(z - __half2float(zh));
    }
}

// ---------------- fused aggregation + LN + residual (layer 2, final) -------
__global__ void __launch_bounds__(256) aggfin_big_kernel(
    const __half* __restrict__ feath, const float* __restrict__ bias,
    const float* __restrict__ lng, const float* __restrict__ lnb,
    const float* __restrict__ res, int resStride, const float* __restrict__ rb,
    const float* __restrict__ rw, float* __restrict__ out)
{
    int wid = (blockIdx.x * blockDim.x + threadIdx.x) >> 5;
    if (wid >= NN) return;
    int lane = threadIdx.x & 31;
    int h = lane & 7;
    int beg = g_off[wid], end = g_off[wid + 1];
    float ald_h = g_ald[wid * HEADS + h];

    float m = -1e30f;
    for (int i = beg + (lane >> 3); i < end; i += 4) {
        int s = g_csr_src[i];
        float ev = g_als[s * HEADS + h] + ald_h;
        ev = ev > 0.f ? ev : 0.2f * ev;
        m = fmaxf(m, ev);
    }
    m = fmaxf(m, __shfl_xor_sync(0xffffffffu, m, 8));
    m = fmaxf(m, __shfl_xor_sync(0xffffffffu, m, 16));
    float ssum = 0.f;
    for (int i = beg + (lane >> 3); i < end; i += 4) {
        int s = g_csr_src[i];
        float ev = g_als[s * HEADS + h] + ald_h;
        ev = ev > 0.f ? ev : 0.2f * ev;
        ssum += expf(ev - m);
    }
    ssum += __shfl_xor_sync(0xffffffffu, ssum, 8);
    ssum += __shfl_xor_sync(0xffffffffu, ssum, 16);
    float inv = 0.125f / (ssum + 1e-16f);   // fold mean-over-heads

    float acc[4] = {0.f, 0.f, 0.f, 0.f};
    for (int i = beg; i < end; i++) {
        int s = g_csr_src[i];
        float ev = g_als[s * HEADS + h] + ald_h;
        ev = ev > 0.f ? ev : 0.2f * ev;
        float alpha = expf(ev - m) * inv;
        const __half* f = feath + (size_t)s * 1024;
#pragma unroll
        for (int hh = 0; hh < 8; hh++) {
            float a = __shfl_sync(0xffffffffu, alpha, hh);
            const __half* fh = f + hh * 128;
#pragma unroll
            for (int ch = 0; ch < 4; ch++)
                acc[ch] += a * __half2float(fh[ch * 32 + lane]);
        }
    }

    // +bias, LN over warp-held 128-dim row, +sig*res (no elu)
    float gval[4];
    float s1 = 0.f, s2 = 0.f;
#pragma unroll
    for (int ch = 0; ch < 4; ch++) {
        float g = acc[ch] + bias[ch * 32 + lane];
        gval[ch] = g; s1 += g; s2 += g * g;
    }
#pragma unroll
    for (int o = 16; o; o >>= 1) {
        s1 += __shfl_xor_sync(0xffffffffu, s1, o);
        s2 += __shfl_xor_sync(0xffffffffu, s2, o);
    }
    float mu = s1 * (1.f / 128.f);
    float var = s2 * (1.f / 128.f) - mu * mu;
    float rs = rsqrtf(var + 1e-5f);
    float sig = 1.f / (1.f + expf(-rw[0]));

#pragma unroll
    for (int ch = 0; ch < 4; ch++) {
        int c = ch * 32 + lane;
        float y = (gval[ch] - mu) * rs * lng[c] + lnb[c];
        float r = res[(size_t)wid * resStride + c] + rb[c];
        out[(size_t)wid * 128 + c] = y + sig * r;
    }
}

// ---------------------------------------------------------------------------
extern "C" void kernel_launch(void* const* d_in, const int* in_sizes, int n_in,
                              void* d_out, int out_size) {
    const float* x   = (const float*)d_in[0];
    const void*  ei  = d_in[1];                   // int32 or int64, detected on device
    const float* W0  = (const float*)d_in[2];
    const float* b0  = (const float*)d_in[3];
    const float* as0 = (const float*)d_in[4];
    const float* ad0 = (const float*)d_in[5];
    const float* lng0= (const float*)d_in[6];
    const float* lnb0= (const float*)d_in[7];
    const float* rW0 = (const float*)d_in[8];
    const float* rb0 = (const float*)d_in[9];
    const float* rw0 = (const float*)d_in[10];
    const float* W1  = (const float*)d_in[11];
    const float* b1  = (const float*)d_in[12];
    const float* as1 = (const float*)d_in[13];
    const float* ad1 = (const float*)d_in[14];
    const float* lng1= (const float*)d_in[15];
    const float* lnb1= (const float*)d_in[16];
    const float* rw1 = (const float*)d_in[17];
    const float* W2  = (const float*)d_in[18];
    const float* b2  = (const float*)d_in[19];
    const float* as2 = (const float*)d_in[20];
    const float* ad2 = (const float*)d_in[21];
    const float* lng2= (const float*)d_in[22];
    const float* lnb2= (const float*)d_in[23];
    const float* rW2 = (const float*)d_in[24];
    const float* rb2 = (const float*)d_in[25];
    const float* rw2 = (const float*)d_in[26];

    float *feat, *act0;
    __half *feath, *Ah, *Al, *Bh;
    cudaGetSymbolAddress((void**)&feat, g_feat);
    cudaGetSymbolAddress((void**)&feath, g_feath);
    cudaGetSymbolAddress((void**)&act0, g_act0);
    cudaGetSymbolAddress((void**)&Ah, g_Ah);
    cudaGetSymbolAddress((void**)&Al, g_Al);
    cudaGetSymbolAddress((void**)&Bh, g_Bh);

    const int TB = 256;
    detect_kernel<<<1, 256>>>((const int*)ei);
    pad_kernel<<<((MP - NN) * 256 + TB - 1) / TB, TB>>>();
    build_edges_kernel<<<(ET + TB - 1) / TB, TB>>>(ei);
    wsplit_kernel<<<(98304 + TB - 1) / TB, TB>>>(W0, rW0, W1, W2, rW2);
    split_kernel<<<(MP * 64 / 4 + TB - 1) / TB, TB>>>(x, Ah, Al, NN * 64, MP * 64);

    int aggBlocks = (NN * 32 + TB - 1) / TB;
    const int MROWS = MP / 128;   // 157

    // ---------------- layer 0 ----------------
    gemm_tc_kernel<<<dim3(4, MROWS), 256>>>(Ah, Al, Bh, feat, feath, 512, 64, 256, as0, ad0, 32);
    // CSR build (needed before agg)
    csr_partial_kernel<<<NBLK, 256>>>();
    csr_scanb_kernel<<<1, 32>>>();
    csr_offsets_kernel<<<NBLK, 256>>>();
    scatter_kernel<<<(ET + TB - 1) / TB, TB>>>();
    aggfin_small_kernel<<<aggBlocks, TB>>>(feath, b0, lng0, lnb0, feat + 256, 512, rb0, rw0, act0, Ah, Al);

    // ---------------- layer 1 ----------------
    gemm_tc_kernel<<<dim3(2, MROWS), 256>>>(Ah, Al, Bh + 32768, feat, feath, 256, 256, 256, as1, ad1, 32);
    aggfin_small_kernel<<<aggBlocks, TB>>>(feath, b1, lng1, lnb1, act0, 256, nullptr, rw1, nullptr, Ah, Al);

    // ---------------- layer 2 ----------------
    gemm_tc_kernel<<<dim3(9, MROWS), 256>>>(Ah, Al, Bh + 98304, feat, feath, 1152, 256, 1024, as2, ad2, 128);
    aggfin_big_kernel<<<aggBlocks, TB>>>(feath, b2, lng2, lnb2, feat + 1024, 1152, rb2, rw2, (float*)d_out);
}